// round 1
// baseline (speedup 1.0000x reference)
#include <cuda_runtime.h>
#include <cstdint>

using ull = unsigned long long;

// ---------------- packed f32x2 helpers (Blackwell PTX 8.6+) ----------------
__device__ __forceinline__ ull pack2(float a, float b) {
    ull r; asm("mov.b64 %0, {%1,%2};" : "=l"(r) : "f"(a), "f"(b)); return r;
}
__device__ __forceinline__ void fma2(ull& d, ull a, ull b) {
    asm("fma.rn.f32x2 %0, %1, %2, %0;" : "+l"(d) : "l"(a), "l"(b));
}
__device__ __forceinline__ float2 unpack2(ull v) {
    float2 r; asm("mov.b64 {%0,%1}, %2;" : "=f"(r.x), "=f"(r.y) : "l"(v)); return r;
}

constexpr int D  = 512;
constexpr int NC = 128;

__device__ float g_cnorm[NC];

// ---------------- kernel 0: codebook squared norms ----------------
__global__ void cnorm_kernel(const float* __restrict__ C) {
    const int c = blockIdx.x;
    const int tid = threadIdx.x;
    float s = 0.f;
    for (int k = tid; k < D; k += 128) {
        float v = C[(size_t)c * D + k];
        s += v * v;
    }
    #pragma unroll
    for (int off = 16; off > 0; off >>= 1)
        s += __shfl_xor_sync(0xffffffffu, s, off);
    __shared__ float ws[4];
    if ((tid & 31) == 0) ws[tid >> 5] = s;
    __syncthreads();
    if (tid == 0) g_cnorm[c] = ws[0] + ws[1] + ws[2] + ws[3];
}

// ---------------- kernel 1: Z = X * W^T + bias (SGEMM, f32x2) ----------------
constexpr int BM = 128, BN = 128, BK = 16;

__global__ void __launch_bounds__(256, 2)
gemm_kernel(const float* __restrict__ X, const float* __restrict__ W,
            const float* __restrict__ bias, float* __restrict__ Z)
{
    __shared__ __align__(16) float As[BK][BM];
    __shared__ __align__(16) float Bs[BK][BN];

    const int tid  = threadIdx.x;
    const int row0 = blockIdx.x * BM;
    const int col0 = blockIdx.y * BN;
    const int tm = tid >> 4;   // 0..15 -> 8 rows each
    const int tn = tid & 15;   // 0..15 -> 8 cols each

    // global->smem load mapping: 512 float4 per tile, 2 per thread
    const int l0 = tid, l1 = tid + 256;
    const int ar0 = l0 >> 2, ak0 = (l0 & 3) * 4;
    const int ar1 = l1 >> 2, ak1 = (l1 & 3) * 4;

    const float* Xp0 = X + (size_t)(row0 + ar0) * D + ak0;
    const float* Xp1 = X + (size_t)(row0 + ar1) * D + ak1;
    const float* Wp0 = W + (size_t)(col0 + ar0) * D + ak0;
    const float* Wp1 = W + (size_t)(col0 + ar1) * D + ak1;

    float4 pa0 = *(const float4*)Xp0;
    float4 pa1 = *(const float4*)Xp1;
    float4 pb0 = *(const float4*)Wp0;
    float4 pb1 = *(const float4*)Wp1;

    ull acc[8][4];
    #pragma unroll
    for (int i = 0; i < 8; ++i)
        #pragma unroll
        for (int j = 0; j < 4; ++j) acc[i][j] = 0ULL;

    for (int kt = 0; kt < D; kt += BK) {
        // commit prefetched tile to smem (transposed to [k][m]/[k][n])
        As[ak0 + 0][ar0] = pa0.x; As[ak0 + 1][ar0] = pa0.y;
        As[ak0 + 2][ar0] = pa0.z; As[ak0 + 3][ar0] = pa0.w;
        As[ak1 + 0][ar1] = pa1.x; As[ak1 + 1][ar1] = pa1.y;
        As[ak1 + 2][ar1] = pa1.z; As[ak1 + 3][ar1] = pa1.w;
        Bs[ak0 + 0][ar0] = pb0.x; Bs[ak0 + 1][ar0] = pb0.y;
        Bs[ak0 + 2][ar0] = pb0.z; Bs[ak0 + 3][ar0] = pb0.w;
        Bs[ak1 + 0][ar1] = pb1.x; Bs[ak1 + 1][ar1] = pb1.y;
        Bs[ak1 + 2][ar1] = pb1.z; Bs[ak1 + 3][ar1] = pb1.w;
        __syncthreads();

        if (kt + BK < D) {  // prefetch next tile while computing
            pa0 = *(const float4*)(Xp0 + kt + BK);
            pa1 = *(const float4*)(Xp1 + kt + BK);
            pb0 = *(const float4*)(Wp0 + kt + BK);
            pb1 = *(const float4*)(Wp1 + kt + BK);
        }

        #pragma unroll
        for (int kk = 0; kk < BK; ++kk) {
            float4 a0 = *(const float4*)&As[kk][tm * 8];
            float4 a1 = *(const float4*)&As[kk][tm * 8 + 4];
            float4 b0 = *(const float4*)&Bs[kk][tn * 8];
            float4 b1 = *(const float4*)&Bs[kk][tn * 8 + 4];
            ull bp0 = pack2(b0.x, b0.y), bp1 = pack2(b0.z, b0.w);
            ull bp2 = pack2(b1.x, b1.y), bp3 = pack2(b1.z, b1.w);
            float av[8] = {a0.x, a0.y, a0.z, a0.w, a1.x, a1.y, a1.z, a1.w};
            #pragma unroll
            for (int i = 0; i < 8; ++i) {
                ull ap = pack2(av[i], av[i]);
                fma2(acc[i][0], ap, bp0);
                fma2(acc[i][1], ap, bp1);
                fma2(acc[i][2], ap, bp2);
                fma2(acc[i][3], ap, bp3);
            }
        }
        __syncthreads();
    }

    const float4 bv0 = *(const float4*)&bias[col0 + tn * 8];
    const float4 bv1 = *(const float4*)&bias[col0 + tn * 8 + 4];
    #pragma unroll
    for (int i = 0; i < 8; ++i) {
        float2 c0 = unpack2(acc[i][0]), c1 = unpack2(acc[i][1]);
        float2 c2 = unpack2(acc[i][2]), c3 = unpack2(acc[i][3]);
        float4 o0 = make_float4(c0.x + bv0.x, c0.y + bv0.y, c1.x + bv0.z, c1.y + bv0.w);
        float4 o1 = make_float4(c2.x + bv1.x, c2.y + bv1.y, c3.x + bv1.z, c3.y + bv1.w);
        float* zr = Z + (size_t)(row0 + tm * 8 + i) * D + col0 + tn * 8;
        *(float4*)zr       = o0;
        *(float4*)(zr + 4) = o1;
    }
}

// ---------------- kernel 2: distances + argmin + gather ----------------
constexpr int VROWS = 64;
constexpr int VTHREADS = 256;
constexpr int ZP = 516;          // padded z row stride (conflict-free LDS)
constexpr int CHUNK = 32;        // codes per smem chunk
constexpr int VQ_SMEM = (VROWS * ZP + D * CHUNK) * (int)sizeof(float);  // 197632 B

__global__ void __launch_bounds__(VTHREADS)
vq_kernel(const float* __restrict__ Z, const float* __restrict__ CB,
          float* __restrict__ Q1, float* __restrict__ Q2)
{
    extern __shared__ float sm[];
    float* zs = sm;                 // [VROWS][ZP]
    float* cs = sm + VROWS * ZP;    // [D][CHUNK] transposed codebook chunk

    const int tid  = threadIdx.x;
    const int row0 = blockIdx.x * VROWS;

    // stage 64 z rows
    #pragma unroll
    for (int it = 0; it < 32; ++it) {
        int li = tid + it * VTHREADS;      // 0..8191 float4 slots
        int r  = li >> 7;                  // 128 float4 per row
        int c4 = (li & 127) * 4;
        float4 v = *(const float4*)(Z + (size_t)(row0 + r) * D + c4);
        *(float4*)(zs + r * ZP + c4) = v;
    }

    const int rg = tid >> 3;           // 0..31 -> rows 2rg, 2rg+1
    const int cg = tid & 7;            // 0..7  -> 4 codes each
    const int r0 = rg * 2, r1 = r0 + 1;
    const int c0 = cg * 4;

    float bestS0 = 3.4e38f, bestS1 = 3.4e38f;
    int   bestI0 = 0,       bestI1 = 0;

    const int jld   = tid & 31;        // code within chunk to load
    const int kbase = (tid >> 5) * 64; // k slice to load

    for (int ch = 0; ch < NC / CHUNK; ++ch) {
        __syncthreads();
        // load chunk transposed: cs[k][j]
        const float4* src = (const float4*)(CB + (size_t)(ch * CHUNK + jld) * D + kbase);
        #pragma unroll
        for (int i = 0; i < 16; ++i) {
            float4 v = src[i];
            int k = kbase + i * 4;
            cs[(k + 0) * CHUNK + jld] = v.x;
            cs[(k + 1) * CHUNK + jld] = v.y;
            cs[(k + 2) * CHUNK + jld] = v.z;
            cs[(k + 3) * CHUNK + jld] = v.w;
        }
        __syncthreads();

        ull a00 = 0, a01 = 0, a10 = 0, a11 = 0;
        #pragma unroll 4
        for (int k = 0; k < D; ++k) {
            float z0 = zs[r0 * ZP + k];
            float z1 = zs[r1 * ZP + k];
            float4 cv = *(const float4*)(cs + k * CHUNK + c0);
            ull cp0 = pack2(cv.x, cv.y);
            ull cp1 = pack2(cv.z, cv.w);
            ull zp0 = pack2(z0, z0);
            ull zp1 = pack2(z1, z1);
            fma2(a00, zp0, cp0); fma2(a01, zp0, cp1);
            fma2(a10, zp1, cp0); fma2(a11, zp1, cp1);
        }
        float2 d0 = unpack2(a00), d1 = unpack2(a01);
        float2 d2 = unpack2(a10), d3 = unpack2(a11);
        float dot0[4] = {d0.x, d0.y, d1.x, d1.y};
        float dot1[4] = {d2.x, d2.y, d3.x, d3.y};
        #pragma unroll
        for (int u = 0; u < 4; ++u) {
            int code = ch * CHUNK + c0 + u;
            float cn = g_cnorm[code];
            float s0 = cn - 2.f * dot0[u];
            float s1 = cn - 2.f * dot1[u];
            if (s0 < bestS0) { bestS0 = s0; bestI0 = code; }   // ascending code order -> first-min tiebreak
            if (s1 < bestS1) { bestS1 = s1; bestI1 = code; }
        }
    }

    // reduce argmin across the 8 code-group lanes (consecutive lanes in warp)
    #pragma unroll
    for (int off = 1; off < 8; off <<= 1) {
        float s0 = __shfl_xor_sync(0xffffffffu, bestS0, off);
        int   i0 = __shfl_xor_sync(0xffffffffu, bestI0, off);
        if (s0 < bestS0 || (s0 == bestS0 && i0 < bestI0)) { bestS0 = s0; bestI0 = i0; }
        float s1 = __shfl_xor_sync(0xffffffffu, bestS1, off);
        int   i1 = __shfl_xor_sync(0xffffffffu, bestI1, off);
        if (s1 < bestS1 || (s1 == bestS1 && i1 < bestI1)) { bestS1 = s1; bestI1 = i1; }
    }

    __syncthreads();
    int* bidx = (int*)cs;   // reuse chunk smem
    if (cg == 0) { bidx[r0] = bestI0; bidx[r1] = bestI1; }
    __syncthreads();

    // gather selected codes, write q twice (q_reshaped region and q region)
    const int w = tid >> 5, lane = tid & 31;
    for (int rr = w; rr < VROWS; rr += 8) {
        int idx = bidx[rr];
        const float4* s4 = (const float4*)(CB + (size_t)idx * D);
        float4* o1 = (float4*)(Q1 + (size_t)(row0 + rr) * D);
        float4* o2 = (float4*)(Q2 + (size_t)(row0 + rr) * D);
        #pragma unroll
        for (int i = lane; i < D / 4; i += 32) {
            float4 v = s4[i];
            o1[i] = v;
            o2[i] = v;
        }
    }
}

// ---------------- launcher ----------------
extern "C" void kernel_launch(void* const* d_in, const int* in_sizes, int n_in,
                              void* d_out, int out_size)
{
    const float* x  = (const float*)d_in[0];
    const float* W  = (const float*)d_in[1];
    const float* b  = (const float*)d_in[2];
    const float* cb = (const float*)d_in[3];

    const int M = in_sizes[0] / D;          // 32768 rows

    float* out = (float*)d_out;
    float* q1 = out;                         // q.reshape(original_shape)
    float* q2 = out + (size_t)M * D;         // q
    float* z  = out + (size_t)2 * M * D;     // z

    cnorm_kernel<<<NC, 128>>>(cb);

    dim3 g(M / BM, D / BN);
    gemm_kernel<<<g, 256>>>(x, W, b, z);

    cudaFuncSetAttribute(vq_kernel, cudaFuncAttributeMaxDynamicSharedMemorySize, VQ_SMEM);
    vq_kernel<<<M / VROWS, VTHREADS, VQ_SMEM>>>(z, cb, q1, q2);
}

// round 3
// speedup vs baseline: 2.2638x; 2.2638x over previous
#include <cuda_runtime.h>
#include <cuda_fp16.h>
#include <cstdint>
#include <cstddef>

#define DEVINL __device__ __forceinline__
using u32 = uint32_t;
using ull = unsigned long long;

constexpr int D  = 512;
constexpr int NC = 128;

__device__ float g_cnorm[NC];

// ---------------------------------------------------------------- helpers
DEVINL u32 smem_u32(const void* p) {
    u32 a;
    asm("{ .reg .u64 t; cvta.to.shared.u64 t, %1; cvt.u32.u64 %0, t; }"
        : "=r"(a) : "l"(p));
    return a;
}

DEVINL void ldsm4(u32& r0, u32& r1, u32& r2, u32& r3, u32 a) {
    asm volatile("ldmatrix.sync.aligned.m8n8.x4.shared.b16 {%0,%1,%2,%3}, [%4];"
                 : "=r"(r0), "=r"(r1), "=r"(r2), "=r"(r3) : "r"(a));
}

DEVINL void mma_f16(float c[4], const u32 a[4], const u32 b[2]) {
    asm volatile(
        "mma.sync.aligned.m16n8k16.row.col.f32.f16.f16.f32 "
        "{%0,%1,%2,%3},{%4,%5,%6,%7},{%8,%9},{%0,%1,%2,%3};"
        : "+f"(c[0]), "+f"(c[1]), "+f"(c[2]), "+f"(c[3])
        : "r"(a[0]), "r"(a[1]), "r"(a[2]), "r"(a[3]), "r"(b[0]), "r"(b[1]));
}

DEVINL u32 pack_h2(__half a, __half b) {
    __half2 h = __halves2half2(a, b);
    return *reinterpret_cast<u32*>(&h);
}

DEVINL void fsplit(float x, __half& h, __half& l) {
    h = __float2half_rn(x);
    l = __float2half_rn(x - __half2float(h));
}

// ---------------------------------------------------------------- cnorm
__global__ void cnorm_kernel(const float* __restrict__ C) {
    const int c = blockIdx.x, tid = threadIdx.x;
    float s = 0.f;
    for (int k = tid; k < D; k += 128) {
        float v = C[(size_t)c * D + k];
        s += v * v;
    }
    #pragma unroll
    for (int off = 16; off > 0; off >>= 1) s += __shfl_xor_sync(0xffffffffu, s, off);
    __shared__ float ws[4];
    if ((tid & 31) == 0) ws[tid >> 5] = s;
    __syncthreads();
    if (tid == 0) g_cnorm[c] = ws[0] + ws[1] + ws[2] + ws[3];
}

// ---------------------------------------------------------------- shared 128x128x512 mainloop
// smem per stage: A tile 16KB + B tile 16KB; double buffered = 64KB.
// tile: 128 rows x 128B; row r data (32 halfs hi + 32 halfs lo):
//   hi 16B-chunk c at chunk (c ^ (r&7)), lo at (c ^ (r&7) ^ 4)  -> conflict-free STS & LDSM.
constexpr int TILE_B   = 16384;
constexpr int STAGE_B  = 2 * TILE_B;   // 32768
constexpr int MAIN_SMEM = 2 * STAGE_B; // 65536

DEVINL void mm_mainloop(const float* __restrict__ aBase,
                        const float* __restrict__ bBase,
                        char* smc, u32 sb, int tid, float acc[4][4][4])
{
    const int lane = tid & 31, w = tid >> 5;
    const int mw = w >> 2, nw = w & 3;       // 2 x 4 warp grid, warp tile 64x32
    const int lr = tid & 127;                // loader row
    const int e  = lr & 7;
    const int eL = lane & 7;

    const float* rp = (tid < 128 ? aBase : bBase) + (size_t)lr * D;
    char* myT = smc + (tid < 128 ? 0 : TILE_B) + lr * 128;

    // ldmatrix per-lane constants
    const int rA  = lane & 15;                 // + mw*64 + mb*16
    const int cAk = lane >> 4;                 // + kk*2
    const int rB0 = nw * 32 + ((lane >> 4) << 3) + (lane & 7);
    const int cBk = (lane >> 3) & 1;

    float4 v[8];
    #pragma unroll
    for (int i = 0; i < 8; ++i) v[i] = ((const float4*)rp)[i];

    #pragma unroll 1
    for (int s = 0; s < 16; ++s) {
        char* tb = myT + (s & 1) * STAGE_B;
        #pragma unroll
        for (int c = 0; c < 4; ++c) {
            float f[8] = { v[2*c].x, v[2*c].y, v[2*c].z, v[2*c].w,
                           v[2*c+1].x, v[2*c+1].y, v[2*c+1].z, v[2*c+1].w };
            __half hh[8], ll[8];
            #pragma unroll
            for (int j = 0; j < 8; ++j) fsplit(f[j], hh[j], ll[j]);
            uint4 uh = make_uint4(pack_h2(hh[0], hh[1]), pack_h2(hh[2], hh[3]),
                                  pack_h2(hh[4], hh[5]), pack_h2(hh[6], hh[7]));
            uint4 ul = make_uint4(pack_h2(ll[0], ll[1]), pack_h2(ll[2], ll[3]),
                                  pack_h2(ll[4], ll[5]), pack_h2(ll[6], ll[7]));
            *(uint4*)(tb + ((c ^ e) << 4))     = uh;
            *(uint4*)(tb + ((c ^ e ^ 4) << 4)) = ul;
        }
        __syncthreads();

        if (s < 15) {
            rp += 32;
            #pragma unroll
            for (int i = 0; i < 8; ++i) v[i] = ((const float4*)rp)[i];
        }

        const u32 aT = sb + (s & 1) * STAGE_B;
        const u32 bT = aT + TILE_B;

        #pragma unroll
        for (int kk = 0; kk < 2; ++kk) {
            u32 ahi[4][4], alo[4][4], bhi[4][2], blo[4][2];
            const int swA = (kk * 2 + cAk) ^ eL;
            #pragma unroll
            for (int mb = 0; mb < 4; ++mb) {
                const u32 base = aT + (mw * 64 + mb * 16 + rA) * 128;
                ldsm4(ahi[mb][0], ahi[mb][1], ahi[mb][2], ahi[mb][3],
                      base + (swA << 4));
                ldsm4(alo[mb][0], alo[mb][1], alo[mb][2], alo[mb][3],
                      base + ((swA ^ 4) << 4));
            }
            const int swB = (kk * 2 + cBk) ^ eL;
            #pragma unroll
            for (int bp = 0; bp < 2; ++bp) {
                const u32 base = bT + (rB0 + bp * 16) * 128;
                u32 r0, r1, r2, r3;
                ldsm4(r0, r1, r2, r3, base + (swB << 4));
                bhi[bp*2][0] = r0; bhi[bp*2][1] = r1;
                bhi[bp*2+1][0] = r2; bhi[bp*2+1][1] = r3;
                ldsm4(r0, r1, r2, r3, base + ((swB ^ 4) << 4));
                blo[bp*2][0] = r0; blo[bp*2][1] = r1;
                blo[bp*2+1][0] = r2; blo[bp*2+1][1] = r3;
            }
            #pragma unroll
            for (int mb = 0; mb < 4; ++mb)
                #pragma unroll
                for (int nb = 0; nb < 4; ++nb) {
                    mma_f16(acc[mb][nb], ahi[mb], bhi[nb]);
                    mma_f16(acc[mb][nb], ahi[mb], blo[nb]);
                    mma_f16(acc[mb][nb], alo[mb], bhi[nb]);
                }
        }
    }
}

// ---------------------------------------------------------------- GEMM: Z = X W^T + b
__global__ void __launch_bounds__(256, 1)
gemm_hmma(const float* __restrict__ X, const float* __restrict__ W,
          const float* __restrict__ bias, float* __restrict__ Z)
{
    extern __shared__ char smc[];
    const u32 sb = smem_u32(smc);
    const int tid = threadIdx.x;
    const int row0 = blockIdx.x * 128, col0 = blockIdx.y * 128;

    float acc[4][4][4] = {};
    mm_mainloop(X + (size_t)row0 * D, W + (size_t)col0 * D, smc, sb, tid, acc);

    const int lane = tid & 31, w = tid >> 5;
    const int mw = w >> 2, nw = w & 3;
    #pragma unroll
    for (int nb = 0; nb < 4; ++nb) {
        const int col = col0 + nw * 32 + nb * 8 + (lane & 3) * 2;
        const float2 bv = *(const float2*)&bias[col];
        #pragma unroll
        for (int mb = 0; mb < 4; ++mb) {
            const int r = row0 + mw * 64 + mb * 16 + (lane >> 2);
            float2 o0 = make_float2(acc[mb][nb][0] + bv.x, acc[mb][nb][1] + bv.y);
            float2 o1 = make_float2(acc[mb][nb][2] + bv.x, acc[mb][nb][3] + bv.y);
            *(float2*)&Z[(size_t)r * D + col]       = o0;
            *(float2*)&Z[(size_t)(r + 8) * D + col] = o1;
        }
    }
}

// ---------------------------------------------------------------- VQ: dots, argmin, gather
constexpr int VQ_SMEM = MAIN_SMEM + 512 + 4096 + 512;  // scn + warpbest + bidx

__global__ void __launch_bounds__(256, 1)
vq_hmma(const float* __restrict__ Z, const float* __restrict__ CB,
        float* __restrict__ Q1, float* __restrict__ Q2)
{
    extern __shared__ char smc[];
    float* scn  = (float*)(smc + MAIN_SMEM);
    ull*   wb   = (ull*)  (smc + MAIN_SMEM + 512);
    int*   bidx = (int*)  (smc + MAIN_SMEM + 512 + 4096);

    const u32 sb = smem_u32(smc);
    const int tid = threadIdx.x;
    const int row0 = blockIdx.x * 128;

    if (tid < NC) scn[tid] = g_cnorm[tid];

    float acc[4][4][4] = {};
    mm_mainloop(Z + (size_t)row0 * D, CB, smc, sb, tid, acc);

    const int lane = tid & 31, w = tid >> 5;
    const int mw = w >> 2, nw = w & 3;

    #pragma unroll
    for (int mb = 0; mb < 4; ++mb) {
        #pragma unroll
        for (int rh = 0; rh < 2; ++rh) {
            ull best = ~0ull;
            #pragma unroll
            for (int nb = 0; nb < 4; ++nb) {
                #pragma unroll
                for (int j = 0; j < 2; ++j) {
                    const int code = nw * 32 + nb * 8 + (lane & 3) * 2 + j;
                    const float sc = fmaf(-2.f, acc[mb][nb][rh * 2 + j], scn[code]);
                    u32 o = __float_as_uint(sc);
                    o = (o & 0x80000000u) ? ~o : (o | 0x80000000u);
                    const ull key = ((ull)o << 32) | (u32)code;
                    if (key < best) best = key;
                }
            }
            ull t = __shfl_xor_sync(0xffffffffu, best, 1); if (t < best) best = t;
            t     = __shfl_xor_sync(0xffffffffu, best, 2); if (t < best) best = t;
            const int rowl = mw * 64 + mb * 16 + rh * 8 + (lane >> 2);
            if ((lane & 3) == 0) wb[rowl * 4 + nw] = best;
        }
    }
    __syncthreads();

    if (tid < 128) {
        ull m = wb[tid * 4];
        ull a = wb[tid * 4 + 1]; if (a < m) m = a;
        a = wb[tid * 4 + 2];     if (a < m) m = a;
        a = wb[tid * 4 + 3];     if (a < m) m = a;
        bidx[tid] = (int)(m & 0xffffffffu);
    }
    __syncthreads();

    for (int rr = w; rr < 128; rr += 8) {
        const int idx = bidx[rr];
        const float4* s4 = (const float4*)(CB + (size_t)idx * D);
        float4* o1 = (float4*)(Q1 + (size_t)(row0 + rr) * D);
        float4* o2 = (float4*)(Q2 + (size_t)(row0 + rr) * D);
        #pragma unroll
        for (int i = lane; i < D / 4; i += 32) {
            const float4 vv = s4[i];
            o1[i] = vv;
            o2[i] = vv;
        }
    }
}

// ---------------------------------------------------------------- launcher
extern "C" void kernel_launch(void* const* d_in, const int* in_sizes, int n_in,
                              void* d_out, int out_size)
{
    const float* x  = (const float*)d_in[0];
    const float* W  = (const float*)d_in[1];
    const float* b  = (const float*)d_in[2];
    const float* cb = (const float*)d_in[3];

    const int M = in_sizes[0] / D;            // 32768

    float* out = (float*)d_out;
    float* q1 = out;
    float* q2 = out + (size_t)M * D;
    float* z  = out + (size_t)2 * M * D;

    cnorm_kernel<<<NC, 128>>>(cb);

    cudaFuncSetAttribute(gemm_hmma, cudaFuncAttributeMaxDynamicSharedMemorySize, MAIN_SMEM);
    gemm_hmma<<<dim3(M / 128, D / 128), 256, MAIN_SMEM>>>(x, W, b, z);

    cudaFuncSetAttribute(vq_hmma, cudaFuncAttributeMaxDynamicSharedMemorySize, VQ_SMEM);
    vq_hmma<<<M / 128, 256, VQ_SMEM>>>(z, cb, q1, q2);
}